// round 7
// baseline (speedup 1.0000x reference)
#include <cuda_runtime.h>
#include <cuda_bf16.h>

// Problem constants (SpectralClassifier: B=1024, S=128, D=768)
#define BB 1024
#define SS 128
#define DD 768
#define H1 256
#define H2 64
#define OUTC 2
#define ROWS 8
#define QTRS 4
#define DET_WORDS 256    // per-block detection sample (1KB, L2-broadcast)
#define KC 12            // k-chunk per smem tile
#define KHALF (DD / 2)   // 384 k per group
#define NCHUNK (KHALF / KC) // 32 chunks per group
#define CHUNKF (KC * H1) // 3072 floats per chunk

// Scratch (no cudaMalloc allowed).
// g_vp holds UNSCALED partial sums: [quarter][b][d]
__device__ float g_vp[QTRS * BB * DD];

// packed dual-fp32 FMA (sm_100+)
#define FMA_F32X2(d, a, b, c) \
    asm("fma.rn.f32x2 %0, %1, %2, %3;" : "=l"(d) : "l"(a), "l"(b), "l"(c))

__device__ __forceinline__ void cpasync16(float* smem_dst, const float* gsrc) {
    unsigned saddr = (unsigned)__cvta_generic_to_shared(smem_dst);
    asm volatile("cp.async.cg.shared.global [%0], [%1], 16;" :: "r"(saddr), "l"(gsrc) : "memory");
}
#define CP_COMMIT()  asm volatile("cp.async.commit_group;" ::: "memory")
#define CP_WAIT(n)   asm volatile("cp.async.wait_group %0;" :: "n"(n) : "memory")

__device__ __forceinline__ bool mask_at(const void* mask, int idx, int mode) {
    if (mode == 0) return ((const int*)mask)[idx] != 0;
    if (mode == 1) return ((const float*)mask)[idx] != 0.0f;
    return ((const unsigned char*)mask)[idx] != 0;
}

// ---------------------------------------------------------------------------
// Kernel A: partial masked seq-sums with inline mask-dtype detection.
// 4096 blocks: blockIdx.x = b*4 + q. Quarter q covers s in [max(1,32q), 32(q+1)).
// (At its DRAM floor — unchanged this round.)
// ---------------------------------------------------------------------------
__global__ void __launch_bounds__(192) reduce_kernel(
    const float* __restrict__ hidden, const void* __restrict__ mask)
{
    __shared__ int s_idx[32];
    __shared__ int s_cnt;
    __shared__ int s_mode;

    const int b   = blockIdx.x >> 2;
    const int q   = blockIdx.x & 3;
    const int lo  = (q == 0) ? 1 : (q * 32);
    const int nrows = (q == 0) ? 31 : 32;
    const int tid = threadIdx.x;

    // --- inline dtype detection on a 256-word sample ---
    {
        int bad_i = 0, bad_f = 0;
        const uint4* w4 = (const uint4*)mask;
        for (int i = tid; i < DET_WORDS / 4; i += 192) {
            uint4 v = __ldg(&w4[i]);
            unsigned arr[4] = {v.x, v.y, v.z, v.w};
            #pragma unroll
            for (int j = 0; j < 4; j++) {
                unsigned u = arr[j];
                if (u > 1u) bad_i = 1;
                float f = __uint_as_float(u);
                if (!(f == 0.0f || f == 1.0f)) bad_f = 1;
            }
        }
        bad_i = __any_sync(0xffffffffu, bad_i);
        bad_f = __any_sync(0xffffffffu, bad_f);
        if (tid == 0) s_mode = 0;
        __syncthreads();
        if ((tid & 31) == 0) {
            int mode = (!bad_i) ? 0 : ((!bad_f) ? 1 : 2);
            atomicMax(&s_mode, mode);
        }
        __syncthreads();
    }
    const int mode = s_mode;

    if (tid < 32) {
        bool m = (tid < nrows) && mask_at(mask, b * SS + lo + tid, mode);
        unsigned bal = __ballot_sync(0xffffffffu, m);
        if (m) s_idx[__popc(bal & ((1u << tid) - 1u))] = lo + tid;
        if (tid == 0) s_cnt = __popc(bal);
    }
    __syncthreads();

    const int cnt = s_cnt;
    const float4* hp = (const float4*)(hidden + (size_t)b * SS * DD);

    float4 a0 = make_float4(0.f, 0.f, 0.f, 0.f);
    float4 a1 = make_float4(0.f, 0.f, 0.f, 0.f);
    float4 a2 = make_float4(0.f, 0.f, 0.f, 0.f);
    float4 a3 = make_float4(0.f, 0.f, 0.f, 0.f);

    int i = 0;
    for (; i + 8 <= cnt; i += 8) {
        float4 x[8];
        #pragma unroll
        for (int u = 0; u < 8; u++)
            x[u] = __ldcs(&hp[s_idx[i + u] * (DD / 4) + tid]);
        a0.x += x[0].x; a0.y += x[0].y; a0.z += x[0].z; a0.w += x[0].w;
        a1.x += x[1].x; a1.y += x[1].y; a1.z += x[1].z; a1.w += x[1].w;
        a2.x += x[2].x; a2.y += x[2].y; a2.z += x[2].z; a2.w += x[2].w;
        a3.x += x[3].x; a3.y += x[3].y; a3.z += x[3].z; a3.w += x[3].w;
        a0.x += x[4].x; a0.y += x[4].y; a0.z += x[4].z; a0.w += x[4].w;
        a1.x += x[5].x; a1.y += x[5].y; a1.z += x[5].z; a1.w += x[5].w;
        a2.x += x[6].x; a2.y += x[6].y; a2.z += x[6].z; a2.w += x[6].w;
        a3.x += x[7].x; a3.y += x[7].y; a3.z += x[7].z; a3.w += x[7].w;
    }
    for (; i < cnt; i++) {
        float4 x0 = __ldcs(&hp[s_idx[i] * (DD / 4) + tid]);
        a0.x += x0.x; a0.y += x0.y; a0.z += x0.z; a0.w += x0.w;
    }

    float4 r;
    r.x = (a0.x + a1.x) + (a2.x + a3.x);
    r.y = (a0.y + a1.y) + (a2.y + a3.y);
    r.z = (a0.z + a1.z) + (a2.z + a3.z);
    r.w = (a0.w + a1.w) + (a2.w + a3.w);
    ((float4*)(g_vp + (size_t)(q * BB + b) * DD))[tid] = r;
}

// ---------------------------------------------------------------------------
// Kernel B: full MLP per 8-row block. 128 blocks x 512 threads.
// In-block k-split: group kg = tid>>8 handles k in [kg*384, kg*384+384).
// Per group: 4-buffer cp.async ring (KC=12), prefetch distance 2,
// ONE __syncthreads per chunk (WAR safe with 4 buffers), batched w-LDS.
// Dynamic smem layout (floats):
//   sW1[2][4][CHUNKF] : 0     .. 24576   (2 groups x 4 bufs x 3072)
//   vs[DD*ROWS]       : 24576 .. 30720
//   h1s[ROWS][H1]     : 30720 .. 32768
//   sW2[H1*H2]        : 32768 .. 49152
//   h2s[ROWS][H2]     : 49152 .. 49664
// ---------------------------------------------------------------------------
#define SMEM_FLOATS 49664
#define OFF_W1  0
#define OFF_VS  24576
#define OFF_H1  30720
#define OFF_W2  32768
#define OFF_H2  49152

__global__ void __launch_bounds__(512) mlp_kernel(
    const float* __restrict__ W1, const float* __restrict__ b1,
    const float* __restrict__ W2, const float* __restrict__ b2,
    const float* __restrict__ W3, const float* __restrict__ b3,
    float* __restrict__ out)
{
    extern __shared__ float smf[];
    float* sW1 = smf + OFF_W1;
    float* vs  = smf + OFF_VS;
    float* h1s = smf + OFF_H1;
    float* sW2 = smf + OFF_W2;
    float* h2s = smf + OFF_H2;

    const int tid = threadIdx.x;
    const int col = tid & (H1 - 1);       // 0..255
    const int kg  = tid >> 8;             // 0 or 1
    const int r0  = blockIdx.x * ROWS;
    const float inv127 = 1.0f / 127.0f;

    float* sW1g = sW1 + kg * 4 * CHUNKF;                 // this group's 4 buffers
    const float* W1g = W1 + (size_t)kg * KHALF * H1;     // this group's k-range

    // --- Prologue: commit order = W2 (G0), chunk0 (G1), chunk1 (G2) ---
    #pragma unroll
    for (int i = 0; i < H1 * H2 / 4; i += 512)
        cpasync16(&sW2[(i + tid) * 4], &W2[(i + tid) * 4]);
    CP_COMMIT();
    #pragma unroll
    for (int i = 0; i < CHUNKF / 4; i += 256)
        cpasync16(&sW1g[0 * CHUNKF + (i + col) * 4], &W1g[0 * CHUNKF + (i + col) * 4]);
    CP_COMMIT();
    #pragma unroll
    for (int i = 0; i < CHUNKF / 4; i += 256)
        cpasync16(&sW1g[1 * CHUNKF + (i + col) * 4], &W1g[1 * CHUNKF + (i + col) * 4]);
    CP_COMMIT();

    // --- Stage v rows while cp.asyncs fly: v = (sum of 4 partials)/127, [k][r] ---
    #pragma unroll
    for (int ii = 0; ii < 3; ii++) {
        int idx = ii * 512 + tid;          // 0..1535 = 8 rows x 192 float4
        int r  = idx / (DD / 4);
        int c4 = idx % (DD / 4);
        const float4* p0 = (const float4*)(g_vp + (size_t)(0 * BB + r0 + r) * DD);
        const float4* p1 = (const float4*)(g_vp + (size_t)(1 * BB + r0 + r) * DD);
        const float4* p2 = (const float4*)(g_vp + (size_t)(2 * BB + r0 + r) * DD);
        const float4* p3 = (const float4*)(g_vp + (size_t)(3 * BB + r0 + r) * DD);
        float4 u0 = __ldg(&p0[c4]);
        float4 u1 = __ldg(&p1[c4]);
        float4 u2 = __ldg(&p2[c4]);
        float4 u3 = __ldg(&p3[c4]);
        float* dst = &vs[(c4 * 4) * ROWS + r];
        dst[0 * ROWS] = ((u0.x + u1.x) + (u2.x + u3.x)) * inv127;
        dst[1 * ROWS] = ((u0.y + u1.y) + (u2.y + u3.y)) * inv127;
        dst[2 * ROWS] = ((u0.z + u1.z) + (u2.z + u3.z)) * inv127;
        dst[3 * ROWS] = ((u0.w + u1.w) + (u2.w + u3.w)) * inv127;
    }

    // --- GEMM1 mainloop: 4-buffer ring, prefetch dist 2, one barrier/chunk ---
    unsigned long long accp[4] = {0ull, 0ull, 0ull, 0ull};

    #pragma unroll 1
    for (int c = 0; c < NCHUNK; c++) {
        if (c < NCHUNK - 2) {
            const int cc = c + 2;
            float* dstb = &sW1g[(cc & 3) * CHUNKF];
            const float* srcb = &W1g[cc * CHUNKF];
            #pragma unroll
            for (int i = 0; i < CHUNKF / 4; i += 256)
                cpasync16(&dstb[(i + col) * 4], &srcb[(i + col) * 4]);
            CP_COMMIT();
            CP_WAIT(2);
        } else if (c == NCHUNK - 2) {
            CP_WAIT(1);
        } else {
            CP_WAIT(0);
        }
        __syncthreads();    // chunk c visible to all; also bounds warp lag to 1

        const float* wbuf = &sW1g[(c & 3) * CHUNKF];
        const float* vk   = &vs[(kg * KHALF + c * KC) * ROWS];

        // batched weight loads: one exposed LDS latency per chunk
        float w[KC];
        #pragma unroll
        for (int kk = 0; kk < KC; kk++)
            w[kk] = wbuf[kk * H1 + col];

        #pragma unroll
        for (int kk = 0; kk < KC; kk++) {
            unsigned long long ww;
            asm("mov.b64 %0, {%1, %1};" : "=l"(ww) : "f"(w[kk]));
            const ulonglong2 va = *(const ulonglong2*)&vk[kk * ROWS];
            const ulonglong2 vb = *(const ulonglong2*)&vk[kk * ROWS + 4];
            FMA_F32X2(accp[0], va.x, ww, accp[0]);
            FMA_F32X2(accp[1], va.y, ww, accp[1]);
            FMA_F32X2(accp[2], vb.x, ww, accp[2]);
            FMA_F32X2(accp[3], vb.y, ww, accp[3]);
        }
    }

    // --- Combine k-split partials: group1 exports, group0 finalizes ---
    __syncthreads();
    if (kg == 1) {
        #pragma unroll
        for (int j = 0; j < 4; j++) {
            float lo, hi;
            asm("mov.b64 {%0, %1}, %2;" : "=f"(lo), "=f"(hi) : "l"(accp[j]));
            h1s[(2 * j) * H1 + col]     = lo;
            h1s[(2 * j + 1) * H1 + col] = hi;
        }
    }
    __syncthreads();
    if (kg == 0) {
        float bias = __ldg(&b1[col]);
        #pragma unroll
        for (int j = 0; j < 4; j++) {
            float lo, hi;
            asm("mov.b64 {%0, %1}, %2;" : "=f"(lo), "=f"(hi) : "l"(accp[j]));
            float p0 = h1s[(2 * j) * H1 + col];
            float p1 = h1s[(2 * j + 1) * H1 + col];
            h1s[(2 * j) * H1 + col]     = fmaxf(lo + p0 + bias, 0.0f);
            h1s[(2 * j + 1) * H1 + col] = fmaxf(hi + p1 + bias, 0.0f);
        }
    }
    __syncthreads();

    // --- GEMM2 (from smem): 512 threads, thread -> (r = t>>6, j = t&63) ---
    {
        const int j = tid & (H2 - 1);
        const int r = tid >> 6;            // 0..7
        float s0 = 0.0f;
        #pragma unroll 16
        for (int k = 0; k < H1; k++)
            s0 = fmaf(h1s[r * H1 + k], sW2[k * H2 + j], s0);
        h2s[r * H2 + j] = fmaxf(s0 + __ldg(&b2[j]), 0.0f);
    }
    __syncthreads();

    // --- GEMM3: 16 outputs (8 rows x 2 logits) ---
    if (tid < ROWS * OUTC) {
        const int r = tid >> 1;
        const int j = tid & 1;
        float s = __ldg(&b3[j]);
        #pragma unroll 8
        for (int c = 0; c < H2; c++)
            s = fmaf(h2s[r * H2 + c], __ldg(&W3[c * OUTC + j]), s);
        out[(size_t)(r0 + r) * OUTC + j] = s;
    }
}

// ---------------------------------------------------------------------------
extern "C" void kernel_launch(void* const* d_in, const int* in_sizes, int n_in,
                              void* d_out, int out_size) {
    const float* hidden = (const float*)d_in[0];
    const void*  mask   = d_in[1];
    const float* W1 = (const float*)d_in[2];
    const float* b1 = (const float*)d_in[3];
    const float* W2 = (const float*)d_in[4];
    const float* b2 = (const float*)d_in[5];
    const float* W3 = (const float*)d_in[6];
    const float* b3 = (const float*)d_in[7];
    float* out = (float*)d_out;

    static int smem_set = 0;
    if (!smem_set) {
        cudaFuncSetAttribute(mlp_kernel,
                             cudaFuncAttributeMaxDynamicSharedMemorySize,
                             SMEM_FLOATS * sizeof(float));
        smem_set = 1;
    }

    reduce_kernel<<<QTRS * BB, 192>>>(hidden, mask);
    mlp_kernel<<<BB / ROWS, 512, SMEM_FLOATS * sizeof(float)>>>(
        W1, b1, W2, b2, W3, b3, out);
}

// round 8
// speedup vs baseline: 1.1506x; 1.1506x over previous
#include <cuda_runtime.h>
#include <cuda_bf16.h>

// Problem constants (SpectralClassifier: B=1024, S=128, D=768)
#define BB 1024
#define SS 128
#define DD 768
#define H1 256
#define H2 64
#define OUTC 2
#define ROWS 8
#define QTRS 4
#define DET_WORDS 256    // per-block detection sample (1KB, L2-broadcast)
#define KGRPS 8          // k-groups in MLP
#define KPER (DD / KGRPS) // 96 k per group

// Scratch (no cudaMalloc allowed).
// g_vp holds UNSCALED partial sums: [quarter][b][d]
__device__ float g_vp[QTRS * BB * DD];

// packed dual-fp32 FMA (sm_100+)
#define FMA_F32X2(d, a, b, c) \
    asm("fma.rn.f32x2 %0, %1, %2, %3;" : "=l"(d) : "l"(a), "l"(b), "l"(c))

__device__ __forceinline__ void cpasync16(float* smem_dst, const float* gsrc) {
    unsigned saddr = (unsigned)__cvta_generic_to_shared(smem_dst);
    asm volatile("cp.async.cg.shared.global [%0], [%1], 16;" :: "r"(saddr), "l"(gsrc) : "memory");
}
#define CP_COMMIT()  asm volatile("cp.async.commit_group;" ::: "memory")
#define CP_WAIT(n)   asm volatile("cp.async.wait_group %0;" :: "n"(n) : "memory")

__device__ __forceinline__ bool mask_at(const void* mask, int idx, int mode) {
    if (mode == 0) return ((const int*)mask)[idx] != 0;
    if (mode == 1) return ((const float*)mask)[idx] != 0.0f;
    return ((const unsigned char*)mask)[idx] != 0;
}

// ---------------------------------------------------------------------------
// Kernel A: partial masked seq-sums with inline mask-dtype detection.
// 4096 blocks: blockIdx.x = b*4 + q. (At its ~31us DRAM floor — unchanged.)
// ---------------------------------------------------------------------------
__global__ void __launch_bounds__(192) reduce_kernel(
    const float* __restrict__ hidden, const void* __restrict__ mask)
{
    __shared__ int s_idx[32];
    __shared__ int s_cnt;
    __shared__ int s_mode;

    const int b   = blockIdx.x >> 2;
    const int q   = blockIdx.x & 3;
    const int lo  = (q == 0) ? 1 : (q * 32);
    const int nrows = (q == 0) ? 31 : 32;
    const int tid = threadIdx.x;

    {
        int bad_i = 0, bad_f = 0;
        const uint4* w4 = (const uint4*)mask;
        for (int i = tid; i < DET_WORDS / 4; i += 192) {
            uint4 v = __ldg(&w4[i]);
            unsigned arr[4] = {v.x, v.y, v.z, v.w};
            #pragma unroll
            for (int j = 0; j < 4; j++) {
                unsigned u = arr[j];
                if (u > 1u) bad_i = 1;
                float f = __uint_as_float(u);
                if (!(f == 0.0f || f == 1.0f)) bad_f = 1;
            }
        }
        bad_i = __any_sync(0xffffffffu, bad_i);
        bad_f = __any_sync(0xffffffffu, bad_f);
        if (tid == 0) s_mode = 0;
        __syncthreads();
        if ((tid & 31) == 0) {
            int mode = (!bad_i) ? 0 : ((!bad_f) ? 1 : 2);
            atomicMax(&s_mode, mode);
        }
        __syncthreads();
    }
    const int mode = s_mode;

    if (tid < 32) {
        bool m = (tid < nrows) && mask_at(mask, b * SS + lo + tid, mode);
        unsigned bal = __ballot_sync(0xffffffffu, m);
        if (m) s_idx[__popc(bal & ((1u << tid) - 1u))] = lo + tid;
        if (tid == 0) s_cnt = __popc(bal);
    }
    __syncthreads();

    const int cnt = s_cnt;
    const float4* hp = (const float4*)(hidden + (size_t)b * SS * DD);

    float4 a0 = make_float4(0.f, 0.f, 0.f, 0.f);
    float4 a1 = make_float4(0.f, 0.f, 0.f, 0.f);
    float4 a2 = make_float4(0.f, 0.f, 0.f, 0.f);
    float4 a3 = make_float4(0.f, 0.f, 0.f, 0.f);

    int i = 0;
    for (; i + 8 <= cnt; i += 8) {
        float4 x[8];
        #pragma unroll
        for (int u = 0; u < 8; u++)
            x[u] = __ldcs(&hp[s_idx[i + u] * (DD / 4) + tid]);
        a0.x += x[0].x; a0.y += x[0].y; a0.z += x[0].z; a0.w += x[0].w;
        a1.x += x[1].x; a1.y += x[1].y; a1.z += x[1].z; a1.w += x[1].w;
        a2.x += x[2].x; a2.y += x[2].y; a2.z += x[2].z; a2.w += x[2].w;
        a3.x += x[3].x; a3.y += x[3].y; a3.z += x[3].z; a3.w += x[3].w;
        a0.x += x[4].x; a0.y += x[4].y; a0.z += x[4].z; a0.w += x[4].w;
        a1.x += x[5].x; a1.y += x[5].y; a1.z += x[5].z; a1.w += x[5].w;
        a2.x += x[6].x; a2.y += x[6].y; a2.z += x[6].z; a2.w += x[6].w;
        a3.x += x[7].x; a3.y += x[7].y; a3.z += x[7].z; a3.w += x[7].w;
    }
    for (; i < cnt; i++) {
        float4 x0 = __ldcs(&hp[s_idx[i] * (DD / 4) + tid]);
        a0.x += x0.x; a0.y += x0.y; a0.z += x0.z; a0.w += x0.w;
    }

    float4 r;
    r.x = (a0.x + a1.x) + (a2.x + a3.x);
    r.y = (a0.y + a1.y) + (a2.y + a3.y);
    r.z = (a0.z + a1.z) + (a2.z + a3.z);
    r.w = (a0.w + a1.w) + (a2.w + a3.w);
    ((float4*)(g_vp + (size_t)(q * BB + b) * DD))[tid] = r;
}

// ---------------------------------------------------------------------------
// Kernel B: full MLP per 8-row block. 128 blocks x 512 threads.
// NO W1 smem staging: W1 streamed via LDG.128 straight to registers.
// Thread t: k-group kg = t>>6 (96 k), cols 4c..4c+3 where c = t&63.
// acc[16] = f32x2-packed [4 cols][4 row-pairs]. Zero-barrier mainloop,
// ping-pong 8-deep LDG.128 double buffer. 8-way partials combined in smem.
// Dynamic smem (floats):
//   vs[DD*ROWS]        : 0     .. 6144
//   h1p[KGRPS][2048]   : 6144  .. 22528   (64 KB partials)
//   h1s[ROWS*H1]       : 22528 .. 24576
//   sW2[H1*H2]         : 24576 .. 40960
//   h2s[ROWS*H2]       : 40960 .. 41472
// ---------------------------------------------------------------------------
#define SMEM_FLOATS 41472
#define OFF_VS   0
#define OFF_H1P  6144
#define OFF_H1S  22528
#define OFF_W2   24576
#define OFF_H2S  40960

// one k-step: w4 = 4 cols' weights; vk points at vs[k][0]
#define KSTEP(w4, vkp) do {                                               \
    unsigned long long w0, w1, w2, w3;                                    \
    asm("mov.b64 %0, {%1, %1};" : "=l"(w0) : "f"((w4).x));                \
    asm("mov.b64 %0, {%1, %1};" : "=l"(w1) : "f"((w4).y));                \
    asm("mov.b64 %0, {%1, %1};" : "=l"(w2) : "f"((w4).z));                \
    asm("mov.b64 %0, {%1, %1};" : "=l"(w3) : "f"((w4).w));                \
    const ulonglong2 va = *(const ulonglong2*)(vkp);                      \
    const ulonglong2 vb = *(const ulonglong2*)((vkp) + 4);                \
    FMA_F32X2(accp[0],  va.x, w0, accp[0]);                               \
    FMA_F32X2(accp[1],  va.y, w0, accp[1]);                               \
    FMA_F32X2(accp[2],  vb.x, w0, accp[2]);                               \
    FMA_F32X2(accp[3],  vb.y, w0, accp[3]);                               \
    FMA_F32X2(accp[4],  va.x, w1, accp[4]);                               \
    FMA_F32X2(accp[5],  va.y, w1, accp[5]);                               \
    FMA_F32X2(accp[6],  vb.x, w1, accp[6]);                               \
    FMA_F32X2(accp[7],  vb.y, w1, accp[7]);                               \
    FMA_F32X2(accp[8],  va.x, w2, accp[8]);                               \
    FMA_F32X2(accp[9],  va.y, w2, accp[9]);                               \
    FMA_F32X2(accp[10], vb.x, w2, accp[10]);                              \
    FMA_F32X2(accp[11], vb.y, w2, accp[11]);                              \
    FMA_F32X2(accp[12], va.x, w3, accp[12]);                              \
    FMA_F32X2(accp[13], va.y, w3, accp[13]);                              \
    FMA_F32X2(accp[14], vb.x, w3, accp[14]);                              \
    FMA_F32X2(accp[15], vb.y, w3, accp[15]);                              \
} while (0)

__global__ void __launch_bounds__(512) mlp_kernel(
    const float* __restrict__ W1, const float* __restrict__ b1,
    const float* __restrict__ W2, const float* __restrict__ b2,
    const float* __restrict__ W3, const float* __restrict__ b3,
    float* __restrict__ out)
{
    extern __shared__ float smf[];
    float* vs  = smf + OFF_VS;
    float* h1p = smf + OFF_H1P;
    float* h1s = smf + OFF_H1S;
    float* sW2 = smf + OFF_W2;
    float* h2s = smf + OFF_H2S;

    const int tid = threadIdx.x;
    const int c   = tid & 63;             // col group: cols 4c..4c+3
    const int kg  = tid >> 6;             // 0..7
    const int r0  = blockIdx.x * ROWS;
    const float inv127 = 1.0f / 127.0f;

    // --- Prologue: stage W2 via cp.async (one group) ---
    #pragma unroll
    for (int i = 0; i < H1 * H2 / 4; i += 512)
        cpasync16(&sW2[(i + tid) * 4], &W2[(i + tid) * 4]);
    CP_COMMIT();

    // --- Stage v rows: v = (sum of 4 quarter partials)/127, layout [k][r] ---
    #pragma unroll
    for (int ii = 0; ii < 3; ii++) {
        int idx = ii * 512 + tid;          // 0..1535 = 8 rows x 192 float4
        int r  = idx / (DD / 4);
        int c4 = idx % (DD / 4);
        const float4* p0 = (const float4*)(g_vp + (size_t)(0 * BB + r0 + r) * DD);
        const float4* p1 = (const float4*)(g_vp + (size_t)(1 * BB + r0 + r) * DD);
        const float4* p2 = (const float4*)(g_vp + (size_t)(2 * BB + r0 + r) * DD);
        const float4* p3 = (const float4*)(g_vp + (size_t)(3 * BB + r0 + r) * DD);
        float4 u0 = __ldg(&p0[c4]);
        float4 u1 = __ldg(&p1[c4]);
        float4 u2 = __ldg(&p2[c4]);
        float4 u3 = __ldg(&p3[c4]);
        float* dst = &vs[(c4 * 4) * ROWS + r];
        dst[0 * ROWS] = ((u0.x + u1.x) + (u2.x + u3.x)) * inv127;
        dst[1 * ROWS] = ((u0.y + u1.y) + (u2.y + u3.y)) * inv127;
        dst[2 * ROWS] = ((u0.z + u1.z) + (u2.z + u3.z)) * inv127;
        dst[3 * ROWS] = ((u0.w + u1.w) + (u2.w + u3.w)) * inv127;
    }
    __syncthreads();

    // --- GEMM1 mainloop: barrier-free, 12 chunks of 8 k-steps, ping-pong ---
    unsigned long long accp[16];
    #pragma unroll
    for (int j = 0; j < 16; j++) accp[j] = 0ull;

    // thread's W1 stream: float4 index (kg*96 + k)*64 + c, advance 64 per k
    const float4* wp = (const float4*)W1 + (size_t)(kg * KPER) * (H1 / 4) + c;
    const float*  vg = &vs[(kg * KPER) * ROWS];

    float4 wA[8], wB[8];
    #pragma unroll
    for (int u = 0; u < 8; u++)
        wA[u] = __ldg(wp + u * 64);
    wp += 8 * 64;

    #pragma unroll 1
    for (int it = 0; it < 6; it++) {
        // prefetch odd chunk
        #pragma unroll
        for (int u = 0; u < 8; u++)
            wB[u] = __ldg(wp + u * 64);
        wp += 8 * 64;
        // compute even chunk (2*it)
        {
            const float* vk = vg + (it * 16) * ROWS;
            #pragma unroll
            for (int u = 0; u < 8; u++)
                KSTEP(wA[u], vk + u * ROWS);
        }
        // prefetch next even chunk (except after last odd)
        if (it < 5) {
            #pragma unroll
            for (int u = 0; u < 8; u++)
                wA[u] = __ldg(wp + u * 64);
            wp += 8 * 64;
        }
        // compute odd chunk (2*it+1)
        {
            const float* vk = vg + (it * 16 + 8) * ROWS;
            #pragma unroll
            for (int u = 0; u < 8; u++)
                KSTEP(wB[u], vk + u * ROWS);
        }
    }

    // --- Write 8-way partials to smem: h1p[kg][r*256 + 4c .. +3] ---
    __syncthreads();   // vs no longer needed; h1p region reuse-safe ordering
    {
        float* hp = h1p + kg * (ROWS * H1);
        #pragma unroll
        for (int j = 0; j < 4; j++) {
            float4 lo4, hi4;
            asm("mov.b64 {%0, %1}, %2;" : "=f"(lo4.x), "=f"(hi4.x) : "l"(accp[0  + j]));
            asm("mov.b64 {%0, %1}, %2;" : "=f"(lo4.y), "=f"(hi4.y) : "l"(accp[4  + j]));
            asm("mov.b64 {%0, %1}, %2;" : "=f"(lo4.z), "=f"(hi4.z) : "l"(accp[8  + j]));
            asm("mov.b64 {%0, %1}, %2;" : "=f"(lo4.w), "=f"(hi4.w) : "l"(accp[12 + j]));
            *(float4*)&hp[(2 * j) * H1 + 4 * c]     = lo4;
            *(float4*)&hp[(2 * j + 1) * H1 + 4 * c] = hi4;
        }
    }
    __syncthreads();

    // --- Reduce 8 partials -> h1s (relu + bias). 512 threads x 4 floats ---
    {
        const int idx = tid * 4;           // 0..2044, row = idx>>8
        const int col = idx & (H1 - 1);
        float4 s = *(const float4*)&h1p[idx];
        #pragma unroll
        for (int g = 1; g < KGRPS; g++) {
            float4 p = *(const float4*)&h1p[g * (ROWS * H1) + idx];
            s.x += p.x; s.y += p.y; s.z += p.z; s.w += p.w;
        }
        float4 bb = *(const float4*)&b1[col];
        s.x = fmaxf(s.x + bb.x, 0.0f);
        s.y = fmaxf(s.y + bb.y, 0.0f);
        s.z = fmaxf(s.z + bb.z, 0.0f);
        s.w = fmaxf(s.w + bb.w, 0.0f);
        *(float4*)&h1s[idx] = s;
    }
    CP_WAIT(0);
    __syncthreads();

    // --- GEMM2 (smem): 512 threads, thread -> (r = t>>6, j = t&63) ---
    {
        const int j = tid & (H2 - 1);
        const int r = tid >> 6;            // 0..7
        float s0 = 0.0f;
        #pragma unroll 16
        for (int k = 0; k < H1; k++)
            s0 = fmaf(h1s[r * H1 + k], sW2[k * H2 + j], s0);
        h2s[r * H2 + j] = fmaxf(s0 + __ldg(&b2[j]), 0.0f);
    }
    __syncthreads();

    // --- GEMM3: 16 outputs (8 rows x 2 logits) ---
    if (tid < ROWS * OUTC) {
        const int r = tid >> 1;
        const int j = tid & 1;
        float s = __ldg(&b3[j]);
        #pragma unroll 8
        for (int cc = 0; cc < H2; cc++)
            s = fmaf(h2s[r * H2 + cc], __ldg(&W3[cc * OUTC + j]), s);
        out[(size_t)(r0 + r) * OUTC + j] = s;
    }
}

// ---------------------------------------------------------------------------
extern "C" void kernel_launch(void* const* d_in, const int* in_sizes, int n_in,
                              void* d_out, int out_size) {
    const float* hidden = (const float*)d_in[0];
    const void*  mask   = d_in[1];
    const float* W1 = (const float*)d_in[2];
    const float* b1 = (const float*)d_in[3];
    const float* W2 = (const float*)d_in[4];
    const float* b2 = (const float*)d_in[5];
    const float* W3 = (const float*)d_in[6];
    const float* b3 = (const float*)d_in[7];
    float* out = (float*)d_out;

    static int smem_set = 0;
    if (!smem_set) {
        cudaFuncSetAttribute(mlp_kernel,
                             cudaFuncAttributeMaxDynamicSharedMemorySize,
                             SMEM_FLOATS * sizeof(float));
        smem_set = 1;
    }

    reduce_kernel<<<QTRS * BB, 192>>>(hidden, mask);
    mlp_kernel<<<BB / ROWS, 512, SMEM_FLOATS * sizeof(float)>>>(
        W1, b1, W2, b2, W3, b3, out);
}